// round 4
// baseline (speedup 1.0000x reference)
#include <cuda_runtime.h>

#define Bsz 4
#define Nn  65536
#define Kk  16
#define Dd  16
#define NK  (Nn * Kk)            // 1048576 = 2^20
#define Ptot (Bsz * NK)          // 4194304

// Scratch (allocation-free rule: __device__ globals)
__device__ float  g_featT[(size_t)Bsz * Nn * Dd];   // (B, N, D) transposed features, 16MB
__device__ float4 g_coordsPad[(size_t)Bsz * Nn];    // (B, N, 4) padded coords, 4MB
__device__ double g_M[35];                          // 7 first + 28 upper-tri second moments
__device__ float4 g_c1[16];                         // per-channel (W0, A.x, A.y, A.z) * scale
__device__ float4 g_c2[16];                         // per-channel (B.x, B.y, B.z, shift)

// ---------------------------------------------------------------------------
// Kernel 0: transpose features (B,D,N)->(B,N,D), pad coords to float4, zero g_M
// ---------------------------------------------------------------------------
__global__ void k_prep(const float* __restrict__ feats,
                       const float* __restrict__ coords) {
    __shared__ float tile[16][129];
    int blk = blockIdx.x;                 // 2048 blocks: 4 batches * 512 tiles
    int b   = blk >> 9;
    int n0  = (blk & 511) * 128;
    int tid = threadIdx.x;                // 256 threads

    if (blk == 0 && tid < 35) g_M[tid] = 0.0;

    if (tid < 128) {
        int n = n0 + tid;
        const float* c = coords + ((size_t)b * Nn + n) * 3;
        g_coordsPad[(size_t)b * Nn + n] = make_float4(c[0], c[1], c[2], 0.f);
    }

    int nn = tid & 127;
    int dd = tid >> 7;                    // 0..1
#pragma unroll
    for (int it = 0; it < 8; it++) {
        int d = dd + it * 2;
        tile[d][nn] = feats[((size_t)(b * 16 + d)) * Nn + n0 + nn];
    }
    __syncthreads();

    int d2 = tid & 15;
    int nb = tid >> 4;                    // 0..15
#pragma unroll
    for (int it = 0; it < 8; it++) {
        int nn2 = nb + it * 16;
        g_featT[((size_t)b * Nn + n0 + nn2) * 16 + d2] = tile[d2][nn2];
    }
}

// ---------------------------------------------------------------------------
// Kernel 1: moments of r7 = [dist, ext(3), nbr(3)] — 4 pairs per thread
// ---------------------------------------------------------------------------
__global__ void k_stats(const int* __restrict__ idx) {
    float acc[35];
#pragma unroll
    for (int i = 0; i < 35; i++) acc[i] = 0.f;

    int t  = blockIdx.x * blockDim.x + threadIdx.x;   // 0 .. Ptot/4-1
    int p0 = t << 2;
    int b  = p0 >> 20;
    int n  = (p0 >> 4) & (Nn - 1);

    int4 jj = ((const int4*)idx)[t];
    const float4* cb = g_coordsPad + (size_t)b * Nn;
    float4 ce = __ldg(cb + n);
    int js[4] = {jj.x, jj.y, jj.z, jj.w};

#pragma unroll
    for (int q = 0; q < 4; q++) {
        float4 cn = __ldg(cb + js[q]);
        float rx = ce.x - cn.x, ry = ce.y - cn.y, rz = ce.z - cn.z;
        float r[7];
        r[0] = sqrtf(rx * rx + ry * ry + rz * rz);
        r[1] = ce.x; r[2] = ce.y; r[3] = ce.z;
        r[4] = cn.x; r[5] = cn.y; r[6] = cn.z;
#pragma unroll
        for (int i = 0; i < 7; i++) acc[i] += r[i];
        int c = 7;
#pragma unroll
        for (int i = 0; i < 7; i++)
#pragma unroll
            for (int qq = i; qq < 7; qq++) acc[c++] += r[i] * r[qq];
    }

#pragma unroll
    for (int i = 0; i < 35; i++)
        for (int off = 16; off; off >>= 1)
            acc[i] += __shfl_down_sync(0xffffffffu, acc[i], off);

    __shared__ float s[8][35];
    int lane = threadIdx.x & 31, w = threadIdx.x >> 5;
    if (lane == 0) {
#pragma unroll
        for (int i = 0; i < 35; i++) s[w][i] = acc[i];
    }
    __syncthreads();
    if (threadIdx.x < 35) {
        float tt = 0.f;
#pragma unroll
        for (int w2 = 0; w2 < 8; w2++) tt += s[w2][threadIdx.x];
        atomicAdd(&g_M[threadIdx.x], (double)tt);
    }
}

// ---------------------------------------------------------------------------
// Kernel 2: analytic BN stats per channel, fold into conv coefficients
// ---------------------------------------------------------------------------
__device__ __forceinline__ int tri_idx(int i, int j) {  // i <= j
    return i * 7 - i * (i - 1) / 2 + (j - i);
}

__global__ void k_finalize(const float* __restrict__ W, const float* __restrict__ bias,
                           const float* __restrict__ gamma, const float* __restrict__ beta) {
    int o = threadIdx.x;
    if (o >= 16) return;
    const double invP = 1.0 / (double)Ptot;
    double m[7];
#pragma unroll
    for (int i = 0; i < 7; i++) m[i] = g_M[i] * invP;

    double a[7];
    a[0] = (double)W[o * 10 + 0];
#pragma unroll
    for (int i = 0; i < 3; i++) a[1 + i] = (double)W[o * 10 + 1 + i] + (double)W[o * 10 + 4 + i];
#pragma unroll
    for (int i = 0; i < 3; i++) a[4 + i] = (double)W[o * 10 + 7 + i] - (double)W[o * 10 + 1 + i];

    double mean = (double)bias[o];
#pragma unroll
    for (int i = 0; i < 7; i++) mean += a[i] * m[i];

    double var = 0.0;
    for (int i = 0; i < 7; i++)
        for (int j = 0; j < 7; j++) {
            int ii = i < j ? i : j, jj = i < j ? j : i;
            double C = g_M[7 + tri_idx(ii, jj)] * invP - m[i] * m[j];
            var += a[i] * a[j] * C;
        }

    double scale = (double)gamma[o] * rsqrt(var + 1e-6);
    double shift = (double)beta[o] + ((double)bias[o] - mean) * scale;
    g_c1[o] = make_float4((float)(a[0] * scale), (float)(a[1] * scale),
                          (float)(a[2] * scale), (float)(a[3] * scale));
    g_c2[o] = make_float4((float)(a[4] * scale), (float)(a[5] * scale),
                          (float)(a[6] * scale), (float)shift);
}

// ---------------------------------------------------------------------------
// Kernel 3: main. Thread = one k-quad. 4-lane groups (same n) cooperate on
// feature gathers: for each k-quad u, lane o loads chunk o (d=4o..4o+3) of
// neighbor (n, 4u+j) -> 1 LDG.128 covers 8 full 64B rows warp-wide.
// ---------------------------------------------------------------------------
__global__ void __launch_bounds__(256)
k_main(const int* __restrict__ idx, float* __restrict__ out) {
    __shared__ float4 sc1[16], sc2[16];
    if (threadIdx.x < 16) { sc1[threadIdx.x] = g_c1[threadIdx.x]; sc2[threadIdx.x] = g_c2[threadIdx.x]; }
    __syncthreads();

    int t  = blockIdx.x * blockDim.x + threadIdx.x;   // 0 .. Ptot/4-1
    int p0 = t << 2;
    int b  = p0 >> 20;
    int n  = (p0 >> 4) & (Nn - 1);
    int o  = t & 3;                                    // k-quad id within group (= lane&3)
    int k0 = o << 2;

    int4 jj = ((const int4*)idx)[t];                   // own quad's neighbors

    // ---------------- feature half: cooperative gather --------------------
    const float4* fT = (const float4*)(g_featT + (size_t)b * Nn * 16);
    float* ob = out + (size_t)b * 32 * NK + (size_t)n * 16;

#pragma unroll
    for (int u = 0; u < 4; u++) {
        // indices of quad u, broadcast from lane u of the 4-lane segment
        int j0 = __shfl_sync(0xffffffffu, jj.x, u, 4);
        int j1 = __shfl_sync(0xffffffffu, jj.y, u, 4);
        int j2 = __shfl_sync(0xffffffffu, jj.z, u, 4);
        int j3 = __shfl_sync(0xffffffffu, jj.w, u, 4);
        // each lane loads its d-chunk (o) of the 4 neighbor rows
        float4 v0 = __ldg(fT + (size_t)j0 * 4 + o);
        float4 v1 = __ldg(fT + (size_t)j1 * 4 + o);
        float4 v2 = __ldg(fT + (size_t)j2 * 4 + o);
        float4 v3 = __ldg(fT + (size_t)j3 * 4 + o);
        const float* a0 = (const float*)&v0;
        const float* a1 = (const float*)&v1;
        const float* a2 = (const float*)&v2;
        const float* a3 = (const float*)&v3;
#pragma unroll
        for (int e = 0; e < 4; e++) {
            // output channel d = 4*o + e, k-quad u
            __stcs((float4*)(ob + (size_t)(4 * o + e) * NK + 4 * u),
                   make_float4(a0[e], a1[e], a2[e], a3[e]));
        }
    }

    // ---------------- geometry half: own quad ------------------------------
    const float4* cb = g_coordsPad + (size_t)b * Nn;
    float4 ce = __ldg(cb + n);
    float4 c0 = __ldg(cb + jj.x);
    float4 c1 = __ldg(cb + jj.y);
    float4 c2 = __ldg(cb + jj.z);
    float4 c3 = __ldg(cb + jj.w);

    float rx, ry, rz;
    rx = ce.x - c0.x; ry = ce.y - c0.y; rz = ce.z - c0.z;
    float d0 = sqrtf(rx * rx + ry * ry + rz * rz);
    rx = ce.x - c1.x; ry = ce.y - c1.y; rz = ce.z - c1.z;
    float d1 = sqrtf(rx * rx + ry * ry + rz * rz);
    rx = ce.x - c2.x; ry = ce.y - c2.y; rz = ce.z - c2.z;
    float d2 = sqrtf(rx * rx + ry * ry + rz * rz);
    rx = ce.x - c3.x; ry = ce.y - c3.y; rz = ce.z - c3.z;
    float d3 = sqrtf(rx * rx + ry * ry + rz * rz);

    float* o2 = ob + (size_t)16 * NK + k0;
#pragma unroll
    for (int d = 0; d < 16; d++) {
        float4 w1 = sc1[d], w2 = sc2[d];
        float ecom = fmaf(w1.y, ce.x, fmaf(w1.z, ce.y, fmaf(w1.w, ce.z, w2.w)));
        float v0 = fmaf(w1.x, d0, fmaf(w2.x, c0.x, fmaf(w2.y, c0.y, fmaf(w2.z, c0.z, ecom))));
        float v1 = fmaf(w1.x, d1, fmaf(w2.x, c1.x, fmaf(w2.y, c1.y, fmaf(w2.z, c1.z, ecom))));
        float v2 = fmaf(w1.x, d2, fmaf(w2.x, c2.x, fmaf(w2.y, c2.y, fmaf(w2.z, c2.z, ecom))));
        float v3 = fmaf(w1.x, d3, fmaf(w2.x, c3.x, fmaf(w2.y, c3.y, fmaf(w2.z, c3.z, ecom))));
        __stcs((float4*)(o2 + (size_t)d * NK),
               make_float4(fmaxf(v0, 0.f), fmaxf(v1, 0.f), fmaxf(v2, 0.f), fmaxf(v3, 0.f)));
    }
}

// ---------------------------------------------------------------------------
extern "C" void kernel_launch(void* const* d_in, const int* in_sizes, int n_in,
                              void* d_out, int out_size) {
    const float* coords = (const float*)d_in[0];
    const float* feats  = (const float*)d_in[1];
    const int*   idx    = (const int*)d_in[2];
    const float* W      = (const float*)d_in[3];
    const float* bias   = (const float*)d_in[4];
    const float* gamma  = (const float*)d_in[5];
    const float* beta   = (const float*)d_in[6];
    float*       out    = (float*)d_out;

    k_prep<<<Bsz * (Nn / 128), 256>>>(feats, coords);
    k_stats<<<(Ptot / 4) / 256, 256>>>(idx);
    k_finalize<<<1, 32>>>(W, bias, gamma, beta);
    k_main<<<(Ptot / 4) / 256, 256>>>(idx, out);
}

// round 5
// speedup vs baseline: 1.3087x; 1.3087x over previous
#include <cuda_runtime.h>

#define Bsz 4
#define Nn  65536
#define Kk  16
#define Dd  16
#define NK  (Nn * Kk)            // 1048576 = 2^20
#define Ptot (Bsz * NK)          // 4194304
#define Tq   (Ptot / 4)          // quad-threads

// Scratch (allocation-free rule: __device__ globals)
__device__ float  g_featT[(size_t)Bsz * Nn * Dd];   // (B, N, D) transposed features, 16MB
__device__ float4 g_coordsPad[(size_t)Bsz * Nn];    // (B, N, 4) padded coords, 4MB
__device__ float4 g_geo[4][Tq];                     // (dist, nx, ny, nz) per pair, r-planes, 67MB
__device__ double g_M[35];                          // 7 first + 28 upper-tri second moments
__device__ float4 g_c1[16];                         // per-channel (W0, A.x, A.y, A.z) * scale
__device__ float4 g_c2[16];                         // per-channel (B.x, B.y, B.z, shift)

// ---------------------------------------------------------------------------
// Kernel 0: transpose features (B,D,N)->(B,N,D), pad coords to float4, zero g_M
// ---------------------------------------------------------------------------
__global__ void k_prep(const float* __restrict__ feats,
                       const float* __restrict__ coords) {
    __shared__ float tile[16][129];
    int blk = blockIdx.x;                 // 2048 blocks: 4 batches * 512 tiles
    int b   = blk >> 9;
    int n0  = (blk & 511) * 128;
    int tid = threadIdx.x;                // 256 threads

    if (blk == 0 && tid < 35) g_M[tid] = 0.0;

    if (tid < 128) {
        int n = n0 + tid;
        const float* c = coords + ((size_t)b * Nn + n) * 3;
        g_coordsPad[(size_t)b * Nn + n] = make_float4(c[0], c[1], c[2], 0.f);
    }

    int nn = tid & 127;
    int dd = tid >> 7;                    // 0..1
#pragma unroll
    for (int it = 0; it < 8; it++) {
        int d = dd + it * 2;
        tile[d][nn] = feats[((size_t)(b * 16 + d)) * Nn + n0 + nn];
    }
    __syncthreads();

    int d2 = tid & 15;
    int nb = tid >> 4;                    // 0..15
#pragma unroll
    for (int it = 0; it < 8; it++) {
        int nn2 = nb + it * 16;
        g_featT[((size_t)b * Nn + n0 + nn2) * 16 + d2] = tile[d2][nn2];
    }
}

// ---------------------------------------------------------------------------
// Kernel 1: moments of r7 AND geo = (dist, nbr coords) per pair (coalesced out)
// ---------------------------------------------------------------------------
__global__ void __launch_bounds__(256)
k_stats(const int* __restrict__ idx) {
    float acc[35];
#pragma unroll
    for (int i = 0; i < 35; i++) acc[i] = 0.f;

    int t  = blockIdx.x * blockDim.x + threadIdx.x;   // 0 .. Tq-1
    int p0 = t << 2;
    int b  = p0 >> 20;
    int n  = (p0 >> 4) & (Nn - 1);

    int4 jj = ((const int4*)idx)[t];
    const float4* cb = g_coordsPad + (size_t)b * Nn;
    float4 ce = __ldg(cb + n);
    int js[4] = {jj.x, jj.y, jj.z, jj.w};

#pragma unroll
    for (int q = 0; q < 4; q++) {
        float4 cn = __ldg(cb + js[q]);
        float rx = ce.x - cn.x, ry = ce.y - cn.y, rz = ce.z - cn.z;
        float dist = sqrtf(rx * rx + ry * ry + rz * rz);
        g_geo[q][t] = make_float4(dist, cn.x, cn.y, cn.z);

        float r[7];
        r[0] = dist;
        r[1] = ce.x; r[2] = ce.y; r[3] = ce.z;
        r[4] = cn.x; r[5] = cn.y; r[6] = cn.z;
#pragma unroll
        for (int i = 0; i < 7; i++) acc[i] += r[i];
        int c = 7;
#pragma unroll
        for (int i = 0; i < 7; i++)
#pragma unroll
            for (int qq = i; qq < 7; qq++) acc[c++] += r[i] * r[qq];
    }

#pragma unroll
    for (int i = 0; i < 35; i++)
        for (int off = 16; off; off >>= 1)
            acc[i] += __shfl_down_sync(0xffffffffu, acc[i], off);

    __shared__ float s[8][35];
    int lane = threadIdx.x & 31, w = threadIdx.x >> 5;
    if (lane == 0) {
#pragma unroll
        for (int i = 0; i < 35; i++) s[w][i] = acc[i];
    }
    __syncthreads();
    if (threadIdx.x < 35) {
        float tt = 0.f;
#pragma unroll
        for (int w2 = 0; w2 < 8; w2++) tt += s[w2][threadIdx.x];
        atomicAdd(&g_M[threadIdx.x], (double)tt);
    }
}

// ---------------------------------------------------------------------------
// Kernel 2: analytic BN stats per channel, fold into conv coefficients
// ---------------------------------------------------------------------------
__device__ __forceinline__ int tri_idx(int i, int j) {  // i <= j
    return i * 7 - i * (i - 1) / 2 + (j - i);
}

__global__ void k_finalize(const float* __restrict__ W, const float* __restrict__ bias,
                           const float* __restrict__ gamma, const float* __restrict__ beta) {
    int o = threadIdx.x;
    if (o >= 16) return;
    const double invP = 1.0 / (double)Ptot;
    double m[7];
#pragma unroll
    for (int i = 0; i < 7; i++) m[i] = g_M[i] * invP;

    double a[7];
    a[0] = (double)W[o * 10 + 0];
#pragma unroll
    for (int i = 0; i < 3; i++) a[1 + i] = (double)W[o * 10 + 1 + i] + (double)W[o * 10 + 4 + i];
#pragma unroll
    for (int i = 0; i < 3; i++) a[4 + i] = (double)W[o * 10 + 7 + i] - (double)W[o * 10 + 1 + i];

    double mean = (double)bias[o];
#pragma unroll
    for (int i = 0; i < 7; i++) mean += a[i] * m[i];

    double var = 0.0;
    for (int i = 0; i < 7; i++)
        for (int j = 0; j < 7; j++) {
            int ii = i < j ? i : j, jj = i < j ? j : i;
            double C = g_M[7 + tri_idx(ii, jj)] * invP - m[i] * m[j];
            var += a[i] * a[j] * C;
        }

    double scale = (double)gamma[o] * rsqrt(var + 1e-6);
    double shift = (double)beta[o] + ((double)bias[o] - mean) * scale;
    g_c1[o] = make_float4((float)(a[0] * scale), (float)(a[1] * scale),
                          (float)(a[2] * scale), (float)(a[3] * scale));
    g_c2[o] = make_float4((float)(a[4] * scale), (float)(a[5] * scale),
                          (float)(a[6] * scale), (float)shift);
}

// ---------------------------------------------------------------------------
// Kernel 3: main — 4 pairs (k-quad) per thread; R3 store pattern (full lines);
// conv inputs come from contiguous geo planes (no scattered coord gather).
// ---------------------------------------------------------------------------
__global__ void __launch_bounds__(256)
k_main(const int* __restrict__ idx, float* __restrict__ out) {
    __shared__ float4 sc1[16], sc2[16];
    if (threadIdx.x < 16) { sc1[threadIdx.x] = g_c1[threadIdx.x]; sc2[threadIdx.x] = g_c2[threadIdx.x]; }
    __syncthreads();

    int t  = blockIdx.x * blockDim.x + threadIdx.x;   // 0 .. Tq-1
    int p0 = t << 2;
    int b  = p0 >> 20;
    int n  = (p0 >> 4) & (Nn - 1);
    int k0 = p0 & 15;                                  // 0, 4, 8, 12

    int4 jj = ((const int4*)idx)[t];

    // contiguous per-pair geometry (dist, nx, ny, nz)
    float4 g0 = __ldg(&g_geo[0][t]);
    float4 g1 = __ldg(&g_geo[1][t]);
    float4 g2 = __ldg(&g_geo[2][t]);
    float4 g3 = __ldg(&g_geo[3][t]);
    float4 ce = __ldg(g_coordsPad + (size_t)b * Nn + n);

    const float* fb = g_featT + (size_t)b * Nn * 16;
    const float4* f0 = (const float4*)(fb + (size_t)jj.x * 16);
    const float4* f1 = (const float4*)(fb + (size_t)jj.y * 16);
    const float4* f2 = (const float4*)(fb + (size_t)jj.z * 16);
    const float4* f3 = (const float4*)(fb + (size_t)jj.w * 16);

    float* o = out + (size_t)b * 32 * NK + (size_t)n * 16 + k0;
#pragma unroll
    for (int q = 0; q < 4; q++) {
        float4 A = __ldg(f0 + q), B = __ldg(f1 + q), C = __ldg(f2 + q), E = __ldg(f3 + q);
        __stcs((float4*)(o + (size_t)(4 * q + 0) * NK), make_float4(A.x, B.x, C.x, E.x));
        __stcs((float4*)(o + (size_t)(4 * q + 1) * NK), make_float4(A.y, B.y, C.y, E.y));
        __stcs((float4*)(o + (size_t)(4 * q + 2) * NK), make_float4(A.z, B.z, C.z, E.z));
        __stcs((float4*)(o + (size_t)(4 * q + 3) * NK), make_float4(A.w, B.w, C.w, E.w));
    }

    float* o2 = o + (size_t)16 * NK;
#pragma unroll
    for (int d = 0; d < 16; d++) {
        float4 w1 = sc1[d], w2 = sc2[d];
        float ecom = fmaf(w1.y, ce.x, fmaf(w1.z, ce.y, fmaf(w1.w, ce.z, w2.w)));
        float v0 = fmaf(w1.x, g0.x, fmaf(w2.x, g0.y, fmaf(w2.y, g0.z, fmaf(w2.z, g0.w, ecom))));
        float v1 = fmaf(w1.x, g1.x, fmaf(w2.x, g1.y, fmaf(w2.y, g1.z, fmaf(w2.z, g1.w, ecom))));
        float v2 = fmaf(w1.x, g2.x, fmaf(w2.x, g2.y, fmaf(w2.y, g2.z, fmaf(w2.z, g2.w, ecom))));
        float v3 = fmaf(w1.x, g3.x, fmaf(w2.x, g3.y, fmaf(w2.y, g3.z, fmaf(w2.z, g3.w, ecom))));
        __stcs((float4*)(o2 + (size_t)d * NK),
               make_float4(fmaxf(v0, 0.f), fmaxf(v1, 0.f), fmaxf(v2, 0.f), fmaxf(v3, 0.f)));
    }
}

// ---------------------------------------------------------------------------
extern "C" void kernel_launch(void* const* d_in, const int* in_sizes, int n_in,
                              void* d_out, int out_size) {
    const float* coords = (const float*)d_in[0];
    const float* feats  = (const float*)d_in[1];
    const int*   idx    = (const int*)d_in[2];
    const float* W      = (const float*)d_in[3];
    const float* bias   = (const float*)d_in[4];
    const float* gamma  = (const float*)d_in[5];
    const float* beta   = (const float*)d_in[6];
    float*       out    = (float*)d_out;

    k_prep<<<Bsz * (Nn / 128), 256>>>(feats, coords);
    k_stats<<<Tq / 256, 256>>>(idx);
    k_finalize<<<1, 32>>>(W, bias, gamma, beta);
    k_main<<<Tq / 256, 256>>>(idx, out);
}

// round 6
// speedup vs baseline: 1.3953x; 1.0662x over previous
#include <cuda_runtime.h>

#define Bsz 4
#define Nn  65536
#define Kk  16
#define Dd  16
#define NK  (Nn * Kk)            // 1048576 = 2^20
#define Ptot (Bsz * NK)          // 4194304
#define Tq   (Ptot / 4)          // quad-threads

// Scratch (allocation-free rule: __device__ globals)
__device__ float  g_featT[(size_t)Bsz * Nn * Dd];   // (B, N, D) transposed features, 16MB
__device__ float4 g_coordsPad[(size_t)Bsz * Nn];    // (B, N, 4) padded coords, 4MB
__device__ float4 g_geo[4][Tq];                     // (dist, nx, ny, nz) per pair, r-planes, 67MB
__device__ double g_M[35];                          // 7 first + 28 upper-tri second moments
__device__ float4 g_c1[16];                         // per-channel (W0, A.x, A.y, A.z) * scale
__device__ float4 g_c2[16];                         // per-channel (B.x, B.y, B.z, shift)

// ---------------------------------------------------------------------------
// Kernel 0: transpose features (B,D,N)->(B,N,D), pad coords to float4, zero g_M
// ---------------------------------------------------------------------------
__global__ void k_prep(const float* __restrict__ feats,
                       const float* __restrict__ coords) {
    __shared__ float tile[16][129];
    int blk = blockIdx.x;                 // 2048 blocks: 4 batches * 512 tiles
    int b   = blk >> 9;
    int n0  = (blk & 511) * 128;
    int tid = threadIdx.x;                // 256 threads

    if (blk == 0 && tid < 35) g_M[tid] = 0.0;

    if (tid < 128) {
        int n = n0 + tid;
        const float* c = coords + ((size_t)b * Nn + n) * 3;
        g_coordsPad[(size_t)b * Nn + n] = make_float4(c[0], c[1], c[2], 0.f);
    }

    int nn = tid & 127;
    int dd = tid >> 7;                    // 0..1
#pragma unroll
    for (int it = 0; it < 8; it++) {
        int d = dd + it * 2;
        tile[d][nn] = feats[((size_t)(b * 16 + d)) * Nn + n0 + nn];
    }
    __syncthreads();

    int d2 = tid & 15;
    int nb = tid >> 4;                    // 0..15
#pragma unroll
    for (int it = 0; it < 8; it++) {
        int nn2 = nb + it * 16;
        g_featT[((size_t)b * Nn + n0 + nn2) * 16 + d2] = tile[d2][nn2];
    }
}

// ---------------------------------------------------------------------------
// Kernel 1: moments of r7 AND geo = (dist, nbr coords) per pair (coalesced out)
// ---------------------------------------------------------------------------
__global__ void __launch_bounds__(256)
k_stats(const int* __restrict__ idx) {
    float acc[35];
#pragma unroll
    for (int i = 0; i < 35; i++) acc[i] = 0.f;

    int t  = blockIdx.x * blockDim.x + threadIdx.x;   // 0 .. Tq-1
    int p0 = t << 2;
    int b  = p0 >> 20;
    int n  = (p0 >> 4) & (Nn - 1);

    int4 jj = ((const int4*)idx)[t];
    const float4* cb = g_coordsPad + (size_t)b * Nn;
    float4 ce = __ldg(cb + n);
    int js[4] = {jj.x, jj.y, jj.z, jj.w};

#pragma unroll
    for (int q = 0; q < 4; q++) {
        float4 cn = __ldg(cb + js[q]);
        float rx = ce.x - cn.x, ry = ce.y - cn.y, rz = ce.z - cn.z;
        float dist = sqrtf(rx * rx + ry * ry + rz * rz);
        g_geo[q][t] = make_float4(dist, cn.x, cn.y, cn.z);

        float r[7];
        r[0] = dist;
        r[1] = ce.x; r[2] = ce.y; r[3] = ce.z;
        r[4] = cn.x; r[5] = cn.y; r[6] = cn.z;
#pragma unroll
        for (int i = 0; i < 7; i++) acc[i] += r[i];
        int c = 7;
#pragma unroll
        for (int i = 0; i < 7; i++)
#pragma unroll
            for (int qq = i; qq < 7; qq++) acc[c++] += r[i] * r[qq];
    }

#pragma unroll
    for (int i = 0; i < 35; i++)
        for (int off = 16; off; off >>= 1)
            acc[i] += __shfl_down_sync(0xffffffffu, acc[i], off);

    __shared__ float s[8][35];
    int lane = threadIdx.x & 31, w = threadIdx.x >> 5;
    if (lane == 0) {
#pragma unroll
        for (int i = 0; i < 35; i++) s[w][i] = acc[i];
    }
    __syncthreads();
    if (threadIdx.x < 35) {
        float tt = 0.f;
#pragma unroll
        for (int w2 = 0; w2 < 8; w2++) tt += s[w2][threadIdx.x];
        atomicAdd(&g_M[threadIdx.x], (double)tt);
    }
}

// ---------------------------------------------------------------------------
// Kernel 2: analytic BN stats per channel, fold into conv coefficients
// ---------------------------------------------------------------------------
__device__ __forceinline__ int tri_idx(int i, int j) {  // i <= j
    return i * 7 - i * (i - 1) / 2 + (j - i);
}

__global__ void k_finalize(const float* __restrict__ W, const float* __restrict__ bias,
                           const float* __restrict__ gamma, const float* __restrict__ beta) {
    int o = threadIdx.x;
    if (o >= 16) return;
    const double invP = 1.0 / (double)Ptot;
    double m[7];
#pragma unroll
    for (int i = 0; i < 7; i++) m[i] = g_M[i] * invP;

    double a[7];
    a[0] = (double)W[o * 10 + 0];
#pragma unroll
    for (int i = 0; i < 3; i++) a[1 + i] = (double)W[o * 10 + 1 + i] + (double)W[o * 10 + 4 + i];
#pragma unroll
    for (int i = 0; i < 3; i++) a[4 + i] = (double)W[o * 10 + 7 + i] - (double)W[o * 10 + 1 + i];

    double mean = (double)bias[o];
#pragma unroll
    for (int i = 0; i < 7; i++) mean += a[i] * m[i];

    double var = 0.0;
    for (int i = 0; i < 7; i++)
        for (int j = 0; j < 7; j++) {
            int ii = i < j ? i : j, jj = i < j ? j : i;
            double C = g_M[7 + tri_idx(ii, jj)] * invP - m[i] * m[j];
            var += a[i] * a[j] * C;
        }

    double scale = (double)gamma[o] * rsqrt(var + 1e-6);
    double shift = (double)beta[o] + ((double)bias[o] - mean) * scale;
    g_c1[o] = make_float4((float)(a[0] * scale), (float)(a[1] * scale),
                          (float)(a[2] * scale), (float)(a[3] * scale));
    g_c2[o] = make_float4((float)(a[4] * scale), (float)(a[5] * scale),
                          (float)(a[6] * scale), (float)shift);
}

// ---------------------------------------------------------------------------
// Kernel 3: main. 4-lane groups share n. Cooperative feature gather (each lane
// loads a 16B chunk of a full 64B row), XOR-swizzled smem transpose, then
// R5-style fully-coalesced plane stores.
// ---------------------------------------------------------------------------
__global__ void __launch_bounds__(128)
k_main(const int* __restrict__ idx, float* __restrict__ out) {
    __shared__ float4 sm[32 * 68];        // 32 groups x (16 slots x 4 chunks + 4 pad)
    __shared__ float4 sc1[16], sc2[16];
    if (threadIdx.x < 16) { sc1[threadIdx.x] = g_c1[threadIdx.x]; sc2[threadIdx.x] = g_c2[threadIdx.x]; }
    __syncthreads();

    int t  = blockIdx.x * blockDim.x + threadIdx.x;   // 0 .. Tq-1
    int p0 = t << 2;
    int b  = p0 >> 20;
    int n  = (p0 >> 4) & (Nn - 1);
    int o  = t & 3;                                    // own k-quad (= lane&3)

    int4 jj = ((const int4*)idx)[t];                   // own quad's neighbor indices

    const float4* fT = (const float4*)(g_featT + (size_t)b * Nn * 16);
    float4* smg = sm + (threadIdx.x >> 2) * 68;

    // ---- cooperative gather: iteration u stages quad u's 4 rows ----------
#pragma unroll
    for (int u = 0; u < 4; u++) {
        int j0 = __shfl_sync(0xffffffffu, jj.x, u, 4);
        int j1 = __shfl_sync(0xffffffffu, jj.y, u, 4);
        int j2 = __shfl_sync(0xffffffffu, jj.z, u, 4);
        int j3 = __shfl_sync(0xffffffffu, jj.w, u, 4);
        float4 v0 = __ldg(fT + (size_t)j0 * 4 + o);    // chunk o of row j0
        float4 v1 = __ldg(fT + (size_t)j1 * 4 + o);
        float4 v2 = __ldg(fT + (size_t)j2 * 4 + o);
        float4 v3 = __ldg(fT + (size_t)j3 * 4 + o);
        int sw = o ^ u;                                // XOR swizzle position
        smg[(4 * u + 0) * 4 + sw] = v0;
        smg[(4 * u + 1) * 4 + sw] = v1;
        smg[(4 * u + 2) * 4 + sw] = v2;
        smg[(4 * u + 3) * 4 + sw] = v3;
    }
    __syncwarp();

    // ---- read back own quad, store fully-coalesced channel planes --------
    float* ob = out + (size_t)b * 32 * NK + (size_t)n * 16 + 4 * o;
#pragma unroll
    for (int q = 0; q < 4; q++) {
        int sw = q ^ o;
        float4 A = smg[(4 * o + 0) * 4 + sw];          // chunk q of own neighbor 0..3
        float4 B = smg[(4 * o + 1) * 4 + sw];
        float4 C = smg[(4 * o + 2) * 4 + sw];
        float4 E = smg[(4 * o + 3) * 4 + sw];
        __stcs((float4*)(ob + (size_t)(4 * q + 0) * NK), make_float4(A.x, B.x, C.x, E.x));
        __stcs((float4*)(ob + (size_t)(4 * q + 1) * NK), make_float4(A.y, B.y, C.y, E.y));
        __stcs((float4*)(ob + (size_t)(4 * q + 2) * NK), make_float4(A.z, B.z, C.z, E.z));
        __stcs((float4*)(ob + (size_t)(4 * q + 3) * NK), make_float4(A.w, B.w, C.w, E.w));
    }

    // ---- conv half: contiguous geo planes ---------------------------------
    float4 g0 = __ldg(&g_geo[0][t]);
    float4 g1 = __ldg(&g_geo[1][t]);
    float4 g2 = __ldg(&g_geo[2][t]);
    float4 g3 = __ldg(&g_geo[3][t]);
    float4 ce = __ldg(g_coordsPad + (size_t)b * Nn + n);

    float* o2 = ob + (size_t)16 * NK;
#pragma unroll
    for (int d = 0; d < 16; d++) {
        float4 w1 = sc1[d], w2 = sc2[d];
        float ecom = fmaf(w1.y, ce.x, fmaf(w1.z, ce.y, fmaf(w1.w, ce.z, w2.w)));
        float v0 = fmaf(w1.x, g0.x, fmaf(w2.x, g0.y, fmaf(w2.y, g0.z, fmaf(w2.z, g0.w, ecom))));
        float v1 = fmaf(w1.x, g1.x, fmaf(w2.x, g1.y, fmaf(w2.y, g1.z, fmaf(w2.z, g1.w, ecom))));
        float v2 = fmaf(w1.x, g2.x, fmaf(w2.x, g2.y, fmaf(w2.y, g2.z, fmaf(w2.z, g2.w, ecom))));
        float v3 = fmaf(w1.x, g3.x, fmaf(w2.x, g3.y, fmaf(w2.y, g3.z, fmaf(w2.z, g3.w, ecom))));
        __stcs((float4*)(o2 + (size_t)d * NK),
               make_float4(fmaxf(v0, 0.f), fmaxf(v1, 0.f), fmaxf(v2, 0.f), fmaxf(v3, 0.f)));
    }
}

// ---------------------------------------------------------------------------
extern "C" void kernel_launch(void* const* d_in, const int* in_sizes, int n_in,
                              void* d_out, int out_size) {
    const float* coords = (const float*)d_in[0];
    const float* feats  = (const float*)d_in[1];
    const int*   idx    = (const int*)d_in[2];
    const float* W      = (const float*)d_in[3];
    const float* bias   = (const float*)d_in[4];
    const float* gamma  = (const float*)d_in[5];
    const float* beta   = (const float*)d_in[6];
    float*       out    = (float*)d_out;

    k_prep<<<Bsz * (Nn / 128), 256>>>(feats, coords);
    k_stats<<<Tq / 256, 256>>>(idx);
    k_finalize<<<1, 32>>>(W, bias, gamma, beta);
    k_main<<<Tq / 128, 128>>>(idx, out);
}

// round 7
// speedup vs baseline: 1.4693x; 1.0530x over previous
#include <cuda_runtime.h>

#define Bsz 4
#define Nn  65536
#define Kk  16
#define Dd  16
#define NK  (Nn * Kk)            // 1048576 = 2^20
#define Ptot (Bsz * NK)          // 4194304
#define Tq   (Ptot / 4)          // quad-threads

// Scratch (allocation-free rule: __device__ globals)
__device__ float  g_featT[(size_t)Bsz * Nn * Dd];   // (B, N, D) transposed features, 16MB
__device__ float4 g_coordsPad[(size_t)Bsz * Nn];    // (B, N, 4) padded coords, 4MB
__device__ double g_M[35];                          // 7 first + 28 upper-tri second moments
__device__ float4 g_c1[16];                         // per-channel (W0, A.x, A.y, A.z) * scale
__device__ float4 g_c2[16];                         // per-channel (B.x, B.y, B.z, shift)

// ---------------------------------------------------------------------------
// Kernel 0: pad coords to float4 (vectorized), zero g_M
// ---------------------------------------------------------------------------
__global__ void __launch_bounds__(256)
k_pad(const float* __restrict__ coords) {
    int t = blockIdx.x * blockDim.x + threadIdx.x;   // 0 .. Bsz*Nn/4 - 1
    if (blockIdx.x == 0 && threadIdx.x < 35) g_M[threadIdx.x] = 0.0;
    // 4 points per thread: 48B in (3 x float4), 64B out (4 x float4)
    const float4* in = (const float4*)coords + (size_t)t * 3;
    float4 a = __ldg(in), bq = __ldg(in + 1), c = __ldg(in + 2);
    float4* o = g_coordsPad + (size_t)t * 4;
    o[0] = make_float4(a.x, a.y, a.z, 0.f);
    o[1] = make_float4(a.w, bq.x, bq.y, 0.f);
    o[2] = make_float4(bq.z, bq.w, c.x, 0.f);
    o[3] = make_float4(c.y, c.z, c.w, 0.f);
}

// ---------------------------------------------------------------------------
// Kernel 1: moments of r7 = [dist, ext(3), nbr(3)]; blocks < 2048 also
// transpose one 128-point tile of features (B,D,N)->(B,N,D).
// ---------------------------------------------------------------------------
__global__ void __launch_bounds__(256)
k_stats(const int* __restrict__ idx, const float* __restrict__ feats) {
    __shared__ float tile[16][129];

    if (blockIdx.x < 2048) {
        int b   = blockIdx.x >> 9;
        int n0  = (blockIdx.x & 511) * 128;
        int tid = threadIdx.x;
        int nn = tid & 127;
        int dd = tid >> 7;                // 0..1
#pragma unroll
        for (int it = 0; it < 8; it++) {
            int d = dd + it * 2;
            tile[d][nn] = feats[((size_t)(b * 16 + d)) * Nn + n0 + nn];
        }
        __syncthreads();
        int d2 = tid & 15;
        int nb = tid >> 4;                // 0..15
#pragma unroll
        for (int it = 0; it < 8; it++) {
            int nn2 = nb + it * 16;
            g_featT[((size_t)b * Nn + n0 + nn2) * 16 + d2] = tile[d2][nn2];
        }
    }

    float acc[35];
#pragma unroll
    for (int i = 0; i < 35; i++) acc[i] = 0.f;

    int t  = blockIdx.x * blockDim.x + threadIdx.x;   // 0 .. Tq-1
    int p0 = t << 2;
    int b  = p0 >> 20;
    int n  = (p0 >> 4) & (Nn - 1);

    int4 jj = ((const int4*)idx)[t];
    const float4* cb = g_coordsPad + (size_t)b * Nn;
    float4 ce = __ldg(cb + n);
    int js[4] = {jj.x, jj.y, jj.z, jj.w};

#pragma unroll
    for (int q = 0; q < 4; q++) {
        float4 cn = __ldg(cb + js[q]);
        float rx = ce.x - cn.x, ry = ce.y - cn.y, rz = ce.z - cn.z;
        float r[7];
        r[0] = sqrtf(rx * rx + ry * ry + rz * rz);
        r[1] = ce.x; r[2] = ce.y; r[3] = ce.z;
        r[4] = cn.x; r[5] = cn.y; r[6] = cn.z;
#pragma unroll
        for (int i = 0; i < 7; i++) acc[i] += r[i];
        int c = 7;
#pragma unroll
        for (int i = 0; i < 7; i++)
#pragma unroll
            for (int qq = i; qq < 7; qq++) acc[c++] += r[i] * r[qq];
    }

#pragma unroll
    for (int i = 0; i < 35; i++)
        for (int off = 16; off; off >>= 1)
            acc[i] += __shfl_down_sync(0xffffffffu, acc[i], off);

    __shared__ float s[8][35];
    int lane = threadIdx.x & 31, w = threadIdx.x >> 5;
    if (lane == 0) {
#pragma unroll
        for (int i = 0; i < 35; i++) s[w][i] = acc[i];
    }
    __syncthreads();
    if (threadIdx.x < 35) {
        float tt = 0.f;
#pragma unroll
        for (int w2 = 0; w2 < 8; w2++) tt += s[w2][threadIdx.x];
        atomicAdd(&g_M[threadIdx.x], (double)tt);
    }
}

// ---------------------------------------------------------------------------
// Kernel 2: analytic BN stats per channel, fold into conv coefficients
// ---------------------------------------------------------------------------
__device__ __forceinline__ int tri_idx(int i, int j) {  // i <= j
    return i * 7 - i * (i - 1) / 2 + (j - i);
}

__global__ void k_finalize(const float* __restrict__ W, const float* __restrict__ bias,
                           const float* __restrict__ gamma, const float* __restrict__ beta) {
    int o = threadIdx.x;
    if (o >= 16) return;
    const double invP = 1.0 / (double)Ptot;
    double m[7];
#pragma unroll
    for (int i = 0; i < 7; i++) m[i] = g_M[i] * invP;

    double a[7];
    a[0] = (double)W[o * 10 + 0];
#pragma unroll
    for (int i = 0; i < 3; i++) a[1 + i] = (double)W[o * 10 + 1 + i] + (double)W[o * 10 + 4 + i];
#pragma unroll
    for (int i = 0; i < 3; i++) a[4 + i] = (double)W[o * 10 + 7 + i] - (double)W[o * 10 + 1 + i];

    double mean = (double)bias[o];
#pragma unroll
    for (int i = 0; i < 7; i++) mean += a[i] * m[i];

    double var = 0.0;
    for (int i = 0; i < 7; i++)
        for (int j = 0; j < 7; j++) {
            int ii = i < j ? i : j, jj = i < j ? j : i;
            double C = g_M[7 + tri_idx(ii, jj)] * invP - m[i] * m[j];
            var += a[i] * a[j] * C;
        }

    double scale = (double)gamma[o] * rsqrt(var + 1e-6);
    double shift = (double)beta[o] + ((double)bias[o] - mean) * scale;
    g_c1[o] = make_float4((float)(a[0] * scale), (float)(a[1] * scale),
                          (float)(a[2] * scale), (float)(a[3] * scale));
    g_c2[o] = make_float4((float)(a[4] * scale), (float)(a[5] * scale),
                          (float)(a[6] * scale), (float)shift);
}

// ---------------------------------------------------------------------------
// Kernel 3: main. 4-lane groups share n. Cooperative feature gather + XOR smem
// transpose + coalesced plane stores. Coords re-gathered (L2-resident), dist
// recomputed — no geo buffer.
// ---------------------------------------------------------------------------
__global__ void __launch_bounds__(128)
k_main(const int* __restrict__ idx, float* __restrict__ out) {
    __shared__ float4 sm[32 * 68];        // 32 groups x (16 slots x 4 chunks + 4 pad)
    __shared__ float4 sc1[16], sc2[16];
    if (threadIdx.x < 16) { sc1[threadIdx.x] = g_c1[threadIdx.x]; sc2[threadIdx.x] = g_c2[threadIdx.x]; }
    __syncthreads();

    int t  = blockIdx.x * blockDim.x + threadIdx.x;   // 0 .. Tq-1
    int p0 = t << 2;
    int b  = p0 >> 20;
    int n  = (p0 >> 4) & (Nn - 1);
    int o  = t & 3;                                    // own k-quad (= lane&3)

    int4 jj = ((const int4*)idx)[t];                   // own quad's neighbor indices

    // issue coord gathers early; consumed after the feature phase
    const float4* cb = g_coordsPad + (size_t)b * Nn;
    float4 ce = __ldg(cb + n);
    float4 c0 = __ldg(cb + jj.x);
    float4 c1 = __ldg(cb + jj.y);
    float4 c2 = __ldg(cb + jj.z);
    float4 c3 = __ldg(cb + jj.w);

    const float4* fT = (const float4*)(g_featT + (size_t)b * Nn * 16);
    float4* smg = sm + (threadIdx.x >> 2) * 68;

    // ---- cooperative gather: iteration u stages quad u's 4 rows ----------
#pragma unroll
    for (int u = 0; u < 4; u++) {
        int j0 = __shfl_sync(0xffffffffu, jj.x, u, 4);
        int j1 = __shfl_sync(0xffffffffu, jj.y, u, 4);
        int j2 = __shfl_sync(0xffffffffu, jj.z, u, 4);
        int j3 = __shfl_sync(0xffffffffu, jj.w, u, 4);
        float4 v0 = __ldg(fT + (size_t)j0 * 4 + o);    // chunk o of row j0
        float4 v1 = __ldg(fT + (size_t)j1 * 4 + o);
        float4 v2 = __ldg(fT + (size_t)j2 * 4 + o);
        float4 v3 = __ldg(fT + (size_t)j3 * 4 + o);
        int sw = o ^ u;                                // XOR swizzle position
        smg[(4 * u + 0) * 4 + sw] = v0;
        smg[(4 * u + 1) * 4 + sw] = v1;
        smg[(4 * u + 2) * 4 + sw] = v2;
        smg[(4 * u + 3) * 4 + sw] = v3;
    }
    __syncwarp();

    // ---- read back own quad, store fully-coalesced channel planes --------
    float* ob = out + (size_t)b * 32 * NK + (size_t)n * 16 + 4 * o;
#pragma unroll
    for (int q = 0; q < 4; q++) {
        int sw = q ^ o;
        float4 A = smg[(4 * o + 0) * 4 + sw];          // chunk q of own neighbor 0..3
        float4 B = smg[(4 * o + 1) * 4 + sw];
        float4 C = smg[(4 * o + 2) * 4 + sw];
        float4 E = smg[(4 * o + 3) * 4 + sw];
        __stcs((float4*)(ob + (size_t)(4 * q + 0) * NK), make_float4(A.x, B.x, C.x, E.x));
        __stcs((float4*)(ob + (size_t)(4 * q + 1) * NK), make_float4(A.y, B.y, C.y, E.y));
        __stcs((float4*)(ob + (size_t)(4 * q + 2) * NK), make_float4(A.z, B.z, C.z, E.z));
        __stcs((float4*)(ob + (size_t)(4 * q + 3) * NK), make_float4(A.w, B.w, C.w, E.w));
    }

    // ---- conv half: recomputed geometry ------------------------------------
    float rx, ry, rz;
    rx = ce.x - c0.x; ry = ce.y - c0.y; rz = ce.z - c0.z;
    float d0 = sqrtf(rx * rx + ry * ry + rz * rz);
    rx = ce.x - c1.x; ry = ce.y - c1.y; rz = ce.z - c1.z;
    float d1 = sqrtf(rx * rx + ry * ry + rz * rz);
    rx = ce.x - c2.x; ry = ce.y - c2.y; rz = ce.z - c2.z;
    float d2 = sqrtf(rx * rx + ry * ry + rz * rz);
    rx = ce.x - c3.x; ry = ce.y - c3.y; rz = ce.z - c3.z;
    float d3 = sqrtf(rx * rx + ry * ry + rz * rz);

    float* o2 = ob + (size_t)16 * NK;
#pragma unroll
    for (int d = 0; d < 16; d++) {
        float4 w1 = sc1[d], w2 = sc2[d];
        float ecom = fmaf(w1.y, ce.x, fmaf(w1.z, ce.y, fmaf(w1.w, ce.z, w2.w)));
        float v0 = fmaf(w1.x, d0, fmaf(w2.x, c0.x, fmaf(w2.y, c0.y, fmaf(w2.z, c0.z, ecom))));
        float v1 = fmaf(w1.x, d1, fmaf(w2.x, c1.x, fmaf(w2.y, c1.y, fmaf(w2.z, c1.z, ecom))));
        float v2 = fmaf(w1.x, d2, fmaf(w2.x, c2.x, fmaf(w2.y, c2.y, fmaf(w2.z, c2.z, ecom))));
        float v3 = fmaf(w1.x, d3, fmaf(w2.x, c3.x, fmaf(w2.y, c3.y, fmaf(w2.z, c3.z, ecom))));
        __stcs((float4*)(o2 + (size_t)d * NK),
               make_float4(fmaxf(v0, 0.f), fmaxf(v1, 0.f), fmaxf(v2, 0.f), fmaxf(v3, 0.f)));
    }
}

// ---------------------------------------------------------------------------
extern "C" void kernel_launch(void* const* d_in, const int* in_sizes, int n_in,
                              void* d_out, int out_size) {
    const float* coords = (const float*)d_in[0];
    const float* feats  = (const float*)d_in[1];
    const int*   idx    = (const int*)d_in[2];
    const float* W      = (const float*)d_in[3];
    const float* bias   = (const float*)d_in[4];
    const float* gamma  = (const float*)d_in[5];
    const float* beta   = (const float*)d_in[6];
    float*       out    = (float*)d_out;

    k_pad<<<(Bsz * Nn / 4) / 256, 256>>>(coords);
    k_stats<<<Tq / 256, 256>>>(idx, feats);
    k_finalize<<<1, 32>>>(W, bias, gamma, beta);
    k_main<<<Tq / 128, 128>>>(idx, out);
}